// round 1
// baseline (speedup 1.0000x reference)
#include <cuda_runtime.h>

// HausdorffDTLoss: B=4, C=2, H=W=256, ALPHA=2
// loss = mean( (pred-gt)^2 * (pred_field^2 + gt_field^2) )
// field^2 per pixel = D_fg + D_bg (exact squared EDT, one term is always 0),
// zeroed per image when the mask has no foreground (detected via D_bg > 1e8).

#define HH 256
#define WW 256
#define BB 4
#define INF9 1.0e9f

// scratch: [batch][type][row*256+col] after the W-pass
// type: 0=pred_fg 1=pred_bg 2=gt_fg 3=gt_bg
__device__ float g_dt[BB][4][HH * WW];
__device__ float g_partial[BB * WW];

// ---------------------------------------------------------------------------
// K1: 1D squared DT along W for all 4 masks. block=(256), grid=(rows, batches)
// ---------------------------------------------------------------------------
__global__ __launch_bounds__(WW) void k_rowpass(const float* __restrict__ mo,
                                                const float* __restrict__ gt) {
    const int r = blockIdx.x;   // row
    const int b = blockIdx.y;   // batch
    const int t = threadIdx.x;  // column

    __shared__ float fp[WW];  // pred fg indicator as 0/INF
    __shared__ float fg[WW];  // gt  fg indicator as 0/INF

    // pred = argmax over 2 channels (ties -> channel 0), fg = pred==1
    float m0 = mo[((b * 2 + 0) * HH + r) * WW + t];
    float m1 = mo[((b * 2 + 1) * HH + r) * WW + t];
    bool pb = (m1 > m0);
    bool gb = (gt[(b * HH + r) * WW + t] > 0.5f);
    fp[t] = pb ? INF9 : 0.0f;
    fg[t] = gb ? INF9 : 0.0f;
    __syncthreads();

    float dpf = 2.0f * INF9, dpb = 2.0f * INF9;
    float dgf = 2.0f * INF9, dgb = 2.0f * INF9;
    const float fi = (float)t;
    float jf = 0.0f;
#pragma unroll 8
    for (int j = 0; j < WW; ++j, jf += 1.0f) {
        float diff = fi - jf;
        float dd = diff * diff;
        float a = fp[j];
        dpf = fminf(dpf, dd + a);
        dpb = fminf(dpb, dd + (INF9 - a));
        float c = fg[j];
        dgf = fminf(dgf, dd + c);
        dgb = fminf(dgb, dd + (INF9 - c));
    }
    const int idx = r * WW + t;
    g_dt[b][0][idx] = dpf;
    g_dt[b][1][idx] = dpb;
    g_dt[b][2][idx] = dgf;
    g_dt[b][3][idx] = dgb;
}

// ---------------------------------------------------------------------------
// K2: 1D squared DT along H for all 4 masks + fused loss terms + block reduce.
// block=(256 rows), grid=(cols, batches)
// ---------------------------------------------------------------------------
__global__ __launch_bounds__(HH) void k_colpass(const float* __restrict__ mo,
                                                const float* __restrict__ gt) {
    const int w = blockIdx.x;   // column
    const int b = blockIdx.y;   // batch
    const int t = threadIdx.x;  // output row i

    __shared__ float s0[HH], s1[HH], s2[HH], s3[HH];
    s0[t] = g_dt[b][0][t * WW + w];
    s1[t] = g_dt[b][1][t * WW + w];
    s2[t] = g_dt[b][2][t * WW + w];
    s3[t] = g_dt[b][3][t * WW + w];
    __syncthreads();

    float d0 = 2.0f * INF9, d1 = 2.0f * INF9;
    float d2 = 2.0f * INF9, d3 = 2.0f * INF9;
    const float fi = (float)t;
    float jf = 0.0f;
#pragma unroll 8
    for (int j = 0; j < HH; ++j, jf += 1.0f) {
        float diff = fi - jf;
        float dd = diff * diff;
        d0 = fminf(d0, dd + s0[j]);
        d1 = fminf(d1, dd + s1[j]);
        d2 = fminf(d2, dd + s2[j]);
        d3 = fminf(d3, dd + s3[j]);
    }

    // pred field^2 (guard: no fg  <=>  D_bg ~ 1e9)
    float f_p = sqrtf(d0) + sqrtf(d1);
    float predsq = (d1 > 1e8f) ? 0.0f : f_p * f_p;
    float f_g = sqrtf(d2) + sqrtf(d3);
    float gtsq = (d3 > 1e8f) ? 0.0f : f_g * f_g;

    // err = (pred - gt)^2  (both binary)
    float m0 = mo[((b * 2 + 0) * HH + t) * WW + w];
    float m1 = mo[((b * 2 + 1) * HH + t) * WW + w];
    float pb = (m1 > m0) ? 1.0f : 0.0f;
    float gv = gt[(b * HH + t) * WW + w];
    float e = pb - gv;
    e = e * e;

    float val = e * (predsq + gtsq);

    // deterministic block reduction
    float sum = val;
#pragma unroll
    for (int o = 16; o > 0; o >>= 1) sum += __shfl_down_sync(0xffffffffu, sum, o);
    __shared__ float wsum[8];
    if ((t & 31) == 0) wsum[t >> 5] = sum;
    __syncthreads();
    if (t < 8) {
        float s = wsum[t];
        s += __shfl_down_sync(0xffu, s, 4);
        s += __shfl_down_sync(0xffu, s, 2);
        s += __shfl_down_sync(0xffu, s, 1);
        if (t == 0) g_partial[b * WW + w] = s;
    }
}

// ---------------------------------------------------------------------------
// K3: final deterministic reduction of 1024 partials -> mean -> d_out[0]
// ---------------------------------------------------------------------------
__global__ __launch_bounds__(256) void k_final(float* __restrict__ out) {
    const int t = threadIdx.x;
    float s = 0.0f;
#pragma unroll
    for (int k = 0; k < 4; ++k) s += g_partial[t + k * 256];
#pragma unroll
    for (int o = 16; o > 0; o >>= 1) s += __shfl_down_sync(0xffffffffu, s, o);
    __shared__ float ws[8];
    if ((t & 31) == 0) ws[t >> 5] = s;
    __syncthreads();
    if (t == 0) {
        float tot = 0.0f;
#pragma unroll
        for (int k = 0; k < 8; ++k) tot += ws[k];
        out[0] = tot * (1.0f / (float)(BB * HH * WW));
    }
}

extern "C" void kernel_launch(void* const* d_in, const int* in_sizes, int n_in,
                              void* d_out, int out_size) {
    const float* mo = (const float*)d_in[0];  // model_output (4,2,256,256) f32
    const float* gt = (const float*)d_in[1];  // ground_truth (4,1,256,256) f32
    float* out = (float*)d_out;

    dim3 grid1(HH, BB);
    k_rowpass<<<grid1, WW>>>(mo, gt);
    dim3 grid2(WW, BB);
    k_colpass<<<grid2, HH>>>(mo, gt);
    k_final<<<1, 256>>>(out);
}

// round 2
// speedup vs baseline: 3.0287x; 3.0287x over previous
#include <cuda_runtime.h>

// HausdorffDTLoss: B=4, C=2, H=W=256, ALPHA=2
// Exact reproduction of the reference's 2-pass brute-force squared EDT:
//  pass1 (binary input): result is exactly (nearest-zero distance)^2, or exactly 1e9
//    when the line has no zero (the j=i term). -> nearest-bit search on a bitmask.
//  pass2: min_j f[j]+(i-j)^2 with exact early exit: once r^2 >= best, no farther j
//    can win (f >= 0). All finite sums are integers < 2^24 (fp32 exact); 1e9 rows
//    reproduce fl(1e9+r^2) >= 1e9, min stays 1e9 -> bit-exact vs reference.

#define HH 256
#define WW 256
#define BB 4
#define INF9 1.0e9f

// planes: 0=pred_fg 1=pred_bg 2=gt_fg 3=gt_bg   (squared DT after row pass)
__device__ float g_dt[BB][4][HH * WW];
__device__ float g_partial[BB * 32];

// ---------------------------------------------------------------------------
// nearest set bit search over an 8-word (256-bit) line bitmask
// ---------------------------------------------------------------------------
__device__ __forceinline__ int nleft_set(const unsigned* w, int i) {
    int k = i >> 5, b = i & 31;
    unsigned m = w[k] & (0xFFFFFFFFu >> (31 - b));
    while (m == 0u) {
        if (--k < 0) return -1000000;
        m = w[k];
    }
    return (k << 5) + 31 - __clz(m);
}
__device__ __forceinline__ int nright_set(const unsigned* w, int i) {
    int k = i >> 5, b = i & 31;
    unsigned m = w[k] & (0xFFFFFFFFu << b);
    while (m == 0u) {
        if (++k > 7) return 1000000;
        m = w[k];
    }
    return (k << 5) + __ffs(m) - 1;
}
__device__ __forceinline__ float dt1(const unsigned* w, int i) {
    int L = nleft_set(w, i);
    int R = nright_set(w, i);
    int d = min(i - L, R - i);
    if (d > 300) return INF9;  // no set bit anywhere in the line
    return (float)(d * d);
}

// ---------------------------------------------------------------------------
// K1: row pass. grid=(256 rows, 4 batches), block=256.
// ---------------------------------------------------------------------------
__global__ __launch_bounds__(256) void k_rowpass(const float* __restrict__ mo,
                                                 const float* __restrict__ gt) {
    const int r = blockIdx.x;
    const int b = blockIdx.y;
    const int t = threadIdx.x;

    __shared__ unsigned P[8], nP[8], G[8], nG[8];

    float m0 = mo[((b * 2 + 0) * HH + r) * WW + t];
    float m1 = mo[((b * 2 + 1) * HH + r) * WW + t];
    bool pb = (m1 > m0);                          // argmax ties -> channel 0
    bool gb = (gt[(b * HH + r) * WW + t] > 0.5f);

    unsigned bp = __ballot_sync(0xFFFFFFFFu, pb);
    unsigned bgm = __ballot_sync(0xFFFFFFFFu, gb);
    if ((t & 31) == 0) {
        int wi = t >> 5;
        P[wi] = bp;
        nP[wi] = ~bp;
        G[wi] = bgm;
        nG[wi] = ~bgm;
    }
    __syncthreads();

    const int idx = r * WW + t;
    g_dt[b][0][idx] = dt1(nP, t);  // edt(pred_fg): dist to nearest non-fg pixel
    g_dt[b][1][idx] = dt1(P, t);   // edt(pred_bg): dist to nearest fg pixel
    g_dt[b][2][idx] = dt1(nG, t);
    g_dt[b][3][idx] = dt1(G, t);
}

// ---------------------------------------------------------------------------
// exact windowed parabola min over a shared-memory column (stride 8 floats)
// ---------------------------------------------------------------------------
__device__ __forceinline__ float wmin(const float* __restrict__ f, int i) {
    float best = f[i * 8];
    for (int r = 1; r < 256; ++r) {
        float rr = (float)(r * r);
        if (rr >= best) break;
        int lo = i - r, hi = i + r;
        if (lo >= 0) best = fminf(best, f[lo * 8] + rr);
        if (hi < 256) best = fminf(best, f[hi * 8] + rr);
    }
    return best;
}

// ---------------------------------------------------------------------------
// K2: column pass + fused loss + block reduction.
// grid=(32 col-groups, 4 batches), block=256. Each block: 8 columns x 256 rows,
// all 4 mask planes. smem tile layout [mask][row*8 + c] -> conflict-free.
// ---------------------------------------------------------------------------
__global__ __launch_bounds__(256) void k_colpass(const float* __restrict__ mo,
                                                 const float* __restrict__ gt) {
    const int cg = blockIdx.x;  // column group (8 cols)
    const int b = blockIdx.y;
    const int t = threadIdx.x;
    const int c = t & 7;    // col within group
    const int r0 = t >> 3;  // 0..31

    __shared__ float tile[4][HH * 8];  // 32 KB

#pragma unroll
    for (int m = 0; m < 4; ++m) {
        const float* src = g_dt[b][m];
#pragma unroll
        for (int k = 0; k < 8; ++k) {
            int row = k * 32 + r0;
            tile[m][row * 8 + c] = src[row * WW + (cg * 8 + c)];
        }
    }
    __syncthreads();

    const int col = cg * 8 + c;
    float acc = 0.0f;
#pragma unroll
    for (int k = 0; k < 8; ++k) {
        int i = k * 32 + r0;  // output row

        float d0 = wmin(&tile[0][c], i);
        float d1 = wmin(&tile[1][c], i);
        float d2 = wmin(&tile[2][c], i);
        float d3 = wmin(&tile[3][c], i);

        float f_p = sqrtf(d0) + sqrtf(d1);
        float predsq = (d1 > 1e8f) ? 0.0f : f_p * f_p;  // no-fg guard (d1==1e9)
        float f_g = sqrtf(d2) + sqrtf(d3);
        float gtsq = (d3 > 1e8f) ? 0.0f : f_g * f_g;

        float m0 = mo[((b * 2 + 0) * HH + i) * WW + col];
        float m1 = mo[((b * 2 + 1) * HH + i) * WW + col];
        float pbv = (m1 > m0) ? 1.0f : 0.0f;
        float gv = gt[(b * HH + i) * WW + col];
        float e = pbv - gv;
        e = e * e;

        acc += e * (predsq + gtsq);
    }

    // deterministic block reduction
#pragma unroll
    for (int o = 16; o > 0; o >>= 1) acc += __shfl_down_sync(0xFFFFFFFFu, acc, o);
    __shared__ float wsum[8];
    if ((t & 31) == 0) wsum[t >> 5] = acc;
    __syncthreads();
    if (t < 8) {
        float s = wsum[t];
        s += __shfl_down_sync(0xFFu, s, 4);
        s += __shfl_down_sync(0xFFu, s, 2);
        s += __shfl_down_sync(0xFFu, s, 1);
        if (t == 0) g_partial[b * 32 + cg] = s;
    }
}

// ---------------------------------------------------------------------------
// K3: final deterministic reduction of 128 partials -> mean
// ---------------------------------------------------------------------------
__global__ __launch_bounds__(128) void k_final(float* __restrict__ out) {
    const int t = threadIdx.x;
    float s = g_partial[t];
#pragma unroll
    for (int o = 16; o > 0; o >>= 1) s += __shfl_down_sync(0xFFFFFFFFu, s, o);
    __shared__ float ws[4];
    if ((t & 31) == 0) ws[t >> 5] = s;
    __syncthreads();
    if (t == 0) {
        out[0] = (ws[0] + ws[1] + ws[2] + ws[3]) * (1.0f / (float)(BB * HH * WW));
    }
}

extern "C" void kernel_launch(void* const* d_in, const int* in_sizes, int n_in,
                              void* d_out, int out_size) {
    const float* mo = (const float*)d_in[0];  // model_output (4,2,256,256) f32
    const float* gt = (const float*)d_in[1];  // ground_truth (4,1,256,256) f32
    float* out = (float*)d_out;

    dim3 grid1(HH, BB);
    k_rowpass<<<grid1, 256>>>(mo, gt);
    dim3 grid2(32, BB);
    k_colpass<<<grid2, 256>>>(mo, gt);
    k_final<<<1, 128>>>(out);
}

// round 3
// speedup vs baseline: 3.9844x; 1.3156x over previous
#include <cuda_runtime.h>

// HausdorffDTLoss: B=4, C=2, H=W=256, ALPHA=2 — bit-exact vs the reference
// 2-pass brute-force squared EDT (see R2 notes; all finite f+r^2 are integers
// < 2^17, fp32-exact; 1e9 rows reproduce fl(1e9+r^2) with min kept at 1e9).
//
// Identities used:
//  - row pass on a binary mask: only the plane matching the pixel's own bit is
//    nontrivial; it equals (nearest OPPOSITE bit distance)^2, or 1e9 if the
//    line is uniform. The other plane is exactly 0.
//  - column pass: D_fg = 0 on bg pixels, D_bg = 0 on fg pixels (j=i term), so
//    one ring search per mask per pixel; field^2 = fl(sqrt(D)^2).
//  - loss term nonzero only where pred_bit != gt_bit (err in {0,1}).
//  - guard: zero the term iff (own bit == 0 && D > 1e8)  [fg-empty image];
//    bg-empty keeps 1e9 like the reference.

#define HH 256
#define WW 256
#define BB 4

// per pixel: x = pred pack (fg16 | bg16<<16), y = gt pack. 0xFFFF == 1e9 sentinel.
__device__ uint2 g_pack[BB][HH * WW];
__device__ float g_partial[128];
__device__ unsigned g_count;  // zero at load; last block resets -> replay-safe

// ---------------------------------------------------------------------------
// nearest opposite-valued bit in a 256-bit row mask
// ---------------------------------------------------------------------------
__device__ __forceinline__ int nearest_opp(const unsigned* __restrict__ w, int i,
                                           unsigned inv) {
    const int k = i >> 5, bpos = i & 31;
    unsigned m = (w[k] ^ inv) & (0xFFFFFFFFu >> (31 - bpos));
    int L = -1000000, kk = k;
    while (true) {
        if (m) { L = (kk << 5) + 31 - __clz(m); break; }
        if (--kk < 0) break;
        m = w[kk] ^ inv;
    }
    m = (w[k] ^ inv) & (0xFFFFFFFFu << bpos);
    int R = 1000000;
    kk = k;
    while (true) {
        if (m) { R = (kk << 5) + __ffs(m) - 1; break; }
        if (++kk > 7) break;
        m = w[kk] ^ inv;
    }
    return min(i - L, R - i);
}

// ---------------------------------------------------------------------------
// K1: row pass. grid=(256 rows, 4 batches), block=256.
// ---------------------------------------------------------------------------
__global__ __launch_bounds__(256) void k_rowpass(const float* __restrict__ mo,
                                                 const float* __restrict__ gt) {
    const int r = blockIdx.x;
    const int b = blockIdx.y;
    const int t = threadIdx.x;

    __shared__ unsigned P[8], G[8];

    float m0 = mo[((b * 2 + 0) * HH + r) * WW + t];
    float m1 = mo[((b * 2 + 1) * HH + r) * WW + t];
    bool pb = (m1 > m0);  // argmax ties -> channel 0
    bool gb = (gt[(b * HH + r) * WW + t] > 0.5f);

    unsigned bp = __ballot_sync(0xFFFFFFFFu, pb);
    unsigned bg = __ballot_sync(0xFFFFFFFFu, gb);
    if ((t & 31) == 0) {
        P[t >> 5] = bp;
        G[t >> 5] = bg;
    }
    __syncthreads();

    int pd = nearest_opp(P, t, pb ? 0xFFFFFFFFu : 0u);
    int gd = nearest_opp(G, t, gb ? 0xFFFFFFFFu : 0u);
    unsigned ps = (pd > 255) ? 0xFFFFu : (unsigned)(pd * pd);
    unsigned gs = (gd > 255) ? 0xFFFFu : (unsigned)(gd * gd);
    uint2 o;
    o.x = pb ? ps : (ps << 16);  // fg16 low, bg16 high
    o.y = gb ? gs : (gs << 16);
    g_pack[b][r * WW + t] = o;
}

// ---------------------------------------------------------------------------
// exact windowed parabola min along a column (stride-8 uint2 tile)
// plane: own-bit side (bit ? fg16/low : bg16/high)
// ---------------------------------------------------------------------------
__device__ __forceinline__ float plane_val(const uint2* __restrict__ col, int j,
                                           bool ymask, bool bit) {
    uint2 v = col[j * 8];
    unsigned w = ymask ? v.y : v.x;
    unsigned s = bit ? (w & 0xFFFFu) : (w >> 16);
    return (s == 0xFFFFu) ? 1.0e9f : (float)s;
}

__device__ __forceinline__ float ringD(const uint2* __restrict__ col, int i,
                                       bool ymask, bool bit) {
    float best = plane_val(col, i, ymask, bit);
#pragma unroll 1
    for (int r = 1; r < 256; ++r) {
        float rr = (float)(r * r);
        if (rr >= best) break;
        int lo = i - r, hi = i + r;
        if (lo >= 0) best = fminf(best, plane_val(col, lo, ymask, bit) + rr);
        if (hi < 256) best = fminf(best, plane_val(col, hi, ymask, bit) + rr);
    }
    return best;
}

// ---------------------------------------------------------------------------
// K2: column pass + fused loss + block reduce + last-block final reduction.
// grid=(32 col-groups, 4 batches), block=256 (c = t&7, r0 = t>>3).
// ---------------------------------------------------------------------------
__global__ __launch_bounds__(256) void k_colpass(float* __restrict__ out) {
    const int cg = blockIdx.x;
    const int b = blockIdx.y;
    const int t = threadIdx.x;
    const int c = t & 7;
    const int r0 = t >> 3;

    __shared__ uint2 tile[HH * 8];  // 16 KB

    const uint2* src = g_pack[b];
#pragma unroll
    for (int k = 0; k < 8; ++k) {
        int row = k * 32 + r0;
        tile[row * 8 + c] = src[row * WW + cg * 8 + c];
    }
    __syncthreads();

    const uint2* col = tile + c;
    float acc = 0.0f;
#pragma unroll 1
    for (int k = 0; k < 8; ++k) {
        int i = k * 32 + r0;
        uint2 v = col[i * 8];
        bool pbit = (v.x & 0xFFFFu) != 0u;
        bool gbit = (v.y & 0xFFFFu) != 0u;
        if (pbit != gbit) {  // err == 1, else term is 0
            float Dp = ringD(col, i, false, pbit);
            float Dg = ringD(col, i, true, gbit);
            float sp = sqrtf(Dp);
            float pterm = sp * sp;  // fl(sqrt(D)^2) bit-exact vs reference
            if (!pbit && Dp > 1e8f) pterm = 0.0f;
            float sg = sqrtf(Dg);
            float gterm = sg * sg;
            if (!gbit && Dg > 1e8f) gterm = 0.0f;
            acc += pterm + gterm;
        }
    }

    // deterministic block reduction
#pragma unroll
    for (int o = 16; o > 0; o >>= 1) acc += __shfl_down_sync(0xFFFFFFFFu, acc, o);
    __shared__ float wsum[8];
    if ((t & 31) == 0) wsum[t >> 5] = acc;
    __syncthreads();
    if (t == 0) {
        float s = 0.0f;
#pragma unroll
        for (int k = 0; k < 8; ++k) s += wsum[k];
        g_partial[b * 32 + cg] = s;
    }

    // last-block-done final reduction (deterministic order)
    __shared__ bool last;
    if (t == 0) {
        __threadfence();
        unsigned done = atomicAdd(&g_count, 1u);
        last = (done == 127u);
    }
    __syncthreads();
    if (last) {
        float s = (t < 128) ? g_partial[t] : 0.0f;
#pragma unroll
        for (int o = 16; o > 0; o >>= 1) s += __shfl_down_sync(0xFFFFFFFFu, s, o);
        if ((t & 31) == 0) wsum[t >> 5] = s;
        __syncthreads();
        if (t == 0) {
            float tot = wsum[0] + wsum[1] + wsum[2] + wsum[3];
            out[0] = tot * (1.0f / (float)(BB * HH * WW));
            g_count = 0;  // reset for next graph replay
        }
    }
}

extern "C" void kernel_launch(void* const* d_in, const int* in_sizes, int n_in,
                              void* d_out, int out_size) {
    const float* mo = (const float*)d_in[0];  // model_output (4,2,256,256) f32
    const float* gt = (const float*)d_in[1];  // ground_truth (4,1,256,256) f32
    float* out = (float*)d_out;

    dim3 grid1(HH, BB);
    k_rowpass<<<grid1, 256>>>(mo, gt);
    dim3 grid2(32, BB);
    k_colpass<<<grid2, 256>>>(out);
}

// round 4
// speedup vs baseline: 4.4054x; 1.1057x over previous
#include <cuda_runtime.h>

// HausdorffDTLoss: B=4, C=2, H=W=256, ALPHA=2 — bit-exact vs the reference
// 2-pass brute-force squared EDT. See prior-round notes for the exactness
// arguments (all finite f+r^2 integers < 2^24; 1e9 sentinel rows reproduce
// fl(1e9+r^2) with the min kept at 1e9; early exit exact since f >= 0).

#define HH 256
#define WW 256
#define BB 4

// per pixel: x = pred pack (fg16 | bg16<<16), y = gt pack. 0xFFFF == 1e9 sentinel.
__device__ uint2 g_pack[BB][HH * WW];
__device__ float g_partial[1024];
__device__ unsigned g_count;  // zero-init at load; last block resets -> replay-safe

// ---------------------------------------------------------------------------
// nearest opposite-valued bit in a 256-bit row mask
// ---------------------------------------------------------------------------
__device__ __forceinline__ int nearest_opp(const unsigned* __restrict__ w, int i,
                                           unsigned inv) {
    const int k = i >> 5, bpos = i & 31;
    unsigned m = (w[k] ^ inv) & (0xFFFFFFFFu >> (31 - bpos));
    int L = -1000000, kk = k;
    while (true) {
        if (m) { L = (kk << 5) + 31 - __clz(m); break; }
        if (--kk < 0) break;
        m = w[kk] ^ inv;
    }
    m = (w[k] ^ inv) & (0xFFFFFFFFu << bpos);
    int R = 1000000;
    kk = k;
    while (true) {
        if (m) { R = (kk << 5) + __ffs(m) - 1; break; }
        if (++kk > 7) break;
        m = w[kk] ^ inv;
    }
    return min(i - L, R - i);
}

// ---------------------------------------------------------------------------
// K1: row pass. grid=(256 rows, 4 batches), block=256.
// ---------------------------------------------------------------------------
__global__ __launch_bounds__(256) void k_rowpass(const float* __restrict__ mo,
                                                 const float* __restrict__ gt) {
    const int r = blockIdx.x;
    const int b = blockIdx.y;
    const int t = threadIdx.x;

    __shared__ unsigned P[8], G[8];

    float m0 = mo[((b * 2 + 0) * HH + r) * WW + t];
    float m1 = mo[((b * 2 + 1) * HH + r) * WW + t];
    bool pb = (m1 > m0);  // argmax ties -> channel 0
    bool gb = (gt[(b * HH + r) * WW + t] > 0.5f);

    unsigned bp = __ballot_sync(0xFFFFFFFFu, pb);
    unsigned bg = __ballot_sync(0xFFFFFFFFu, gb);
    if ((t & 31) == 0) {
        P[t >> 5] = bp;
        G[t >> 5] = bg;
    }
    __syncthreads();

    int pd = nearest_opp(P, t, pb ? 0xFFFFFFFFu : 0u);
    int gd = nearest_opp(G, t, gb ? 0xFFFFFFFFu : 0u);
    unsigned ps = (pd > 255) ? 0xFFFFu : (unsigned)(pd * pd);
    unsigned gs = (gd > 255) ? 0xFFFFu : (unsigned)(gd * gd);
    uint2 o;
    o.x = pb ? ps : (ps << 16);  // own-bit plane in low 16, other in high 16
    o.y = gb ? gs : (gs << 16);
    g_pack[b][r * WW + t] = o;
}

// ---------------------------------------------------------------------------
// plane unpack: ym selects gt pack, bit selects fg(low)/bg(high) half
// ---------------------------------------------------------------------------
__device__ __forceinline__ float upk(uint2 v, bool ym, bool bit) {
    unsigned w = ym ? v.y : v.x;
    unsigned s = bit ? (w & 0xFFFFu) : (w >> 16);
    return (s == 0xFFFFu) ? 1.0e9f : (float)s;
}

__device__ __forceinline__ float gplane(const uint2* __restrict__ src, int row,
                                        int col, bool ym, bool bit) {
    return upk(__ldg(&src[row * WW + col]), ym, bit);
}

// search: tile rows cover global rows [base, base+95], i is global, ti = i-base.
// halo entries are all-sentinel so r<=32 needs no bounds checks.
__device__ __forceinline__ float ringD(const uint2* __restrict__ tcol, int ti,
                                       const uint2* __restrict__ src, int i,
                                       int col, bool ym, bool bit) {
    float best = upk(tcol[ti * 8], ym, bit);
#pragma unroll 1
    for (int r = 1; r <= 32; ++r) {
        float rr = (float)(r * r);
        if (rr >= best) return best;
        best = fminf(best, upk(tcol[(ti - r) * 8], ym, bit) + rr);
        best = fminf(best, upk(tcol[(ti + r) * 8], ym, bit) + rr);
    }
    if (best > 1024.0f) {  // rare exact fallback beyond the tile halo
#pragma unroll 1
        for (int r = 33; r < 256; ++r) {
            float rr = (float)(r * r);
            if (rr >= best) break;
            int lo = i - r, hi = i + r;
            if (lo >= 0) best = fminf(best, gplane(src, lo, col, ym, bit) + rr);
            if (hi < 256) best = fminf(best, gplane(src, hi, col, ym, bit) + rr);
        }
    }
    return best;
}

// ---------------------------------------------------------------------------
// K2: column pass + fused loss. grid=(32 colgroups, 8 rowtiles, 4 batches),
// block=256: one thread per output pixel (c = t&7, row = ry*32 + t>>3).
// ---------------------------------------------------------------------------
__global__ __launch_bounds__(256) void k_colpass(float* __restrict__ out) {
    const int cg = blockIdx.x;
    const int ry = blockIdx.y;
    const int b = blockIdx.z;
    const int t = threadIdx.x;
    const int c = t & 7;
    const int base = ry * 32 - 32;

    __shared__ uint2 tile[96 * 8];  // 6 KB

    const uint2* src = g_pack[b];
#pragma unroll
    for (int k = 0; k < 3; ++k) {
        int idx = t + k * 256;
        int trow = idx >> 3, c2 = idx & 7;
        int grow = base + trow;
        uint2 v = make_uint2(0xFFFFFFFFu, 0xFFFFFFFFu);  // halo = all-sentinel
        if (grow >= 0 && grow < HH) v = __ldg(&src[grow * WW + cg * 8 + c2]);
        tile[idx] = v;
    }
    __syncthreads();

    const int i = ry * 32 + (t >> 3);  // global output row
    const int ti = i - base;           // tile row (= 32 + t>>3)
    const int col = cg * 8 + c;
    const uint2* tcol = tile + c;

    float acc = 0.0f;
    uint2 v = tcol[ti * 8];
    bool pbit = (v.x & 0xFFFFu) != 0u;
    bool gbit = (v.y & 0xFFFFu) != 0u;
    if (pbit != gbit) {  // err == 1, else term is 0
        float Dp = ringD(tcol, ti, src, i, col, false, pbit);
        float Dg = ringD(tcol, ti, src, i, col, true, gbit);
        float sp = sqrtf(Dp);
        float pterm = sp * sp;  // fl(sqrt(D)^2): bit-exact vs reference
        if (!pbit && Dp > 1e8f) pterm = 0.0f;  // fg-empty guard
        float sg = sqrtf(Dg);
        float gterm = sg * sg;
        if (!gbit && Dg > 1e8f) gterm = 0.0f;
        acc = pterm + gterm;
    }

    // deterministic block reduction
#pragma unroll
    for (int o = 16; o > 0; o >>= 1) acc += __shfl_down_sync(0xFFFFFFFFu, acc, o);
    __shared__ float wsum[8];
    if ((t & 31) == 0) wsum[t >> 5] = acc;
    __syncthreads();
    if (t == 0) {
        float s = 0.0f;
#pragma unroll
        for (int k = 0; k < 8; ++k) s += wsum[k];
        g_partial[((b * 8 + ry) * 32) + cg] = s;
    }

    // last-block-done final reduction (deterministic order)
    __shared__ bool last;
    if (t == 0) {
        __threadfence();
        unsigned done = atomicAdd(&g_count, 1u);
        last = (done == 1023u);
    }
    __syncthreads();
    if (last) {
        float s = g_partial[t] + g_partial[t + 256] + g_partial[t + 512] +
                  g_partial[t + 768];
#pragma unroll
        for (int o = 16; o > 0; o >>= 1) s += __shfl_down_sync(0xFFFFFFFFu, s, o);
        if ((t & 31) == 0) wsum[t >> 5] = s;
        __syncthreads();
        if (t == 0) {
            float tot = 0.0f;
#pragma unroll
            for (int k = 0; k < 8; ++k) tot += wsum[k];
            out[0] = tot * (1.0f / (float)(BB * HH * WW));
            g_count = 0;  // reset for next graph replay
        }
    }
}

extern "C" void kernel_launch(void* const* d_in, const int* in_sizes, int n_in,
                              void* d_out, int out_size) {
    const float* mo = (const float*)d_in[0];  // model_output (4,2,256,256) f32
    const float* gt = (const float*)d_in[1];  // ground_truth (4,1,256,256) f32
    float* out = (float*)d_out;

    dim3 grid1(HH, BB);
    k_rowpass<<<grid1, 256>>>(mo, gt);
    dim3 grid2(32, 8, BB);
    k_colpass<<<grid2, 256>>>(out);
}